// round 16
// baseline (speedup 1.0000x reference)
#include <cuda_runtime.h>
#include <cuda_bf16.h>
#include <math.h>
#include <stdint.h>

#define M_TOK   100352
#define C_DIM   192
#define NHEADS  6
#define HDIM    32
#define HIDDEN  768

// GEMM-64 tiling
#define BM 128
#define BN 64
#define BK 32
#define RPB 80
#define OFF_A  0
#define OFF_B  (BM*RPB)
#define STAGE_BYTES (BM*RPB + BN*RPB)
#define NSTAGE 4
// GEMM-192 tiling
#define BM2 64
#define BN2 192
#define OFF_B2 (BM2*RPB)
#define STAGE2 (BM2*RPB + BN2*RPB)

// attention smem layout (per pair)
#define AQ   0              // Q [64][80B]
#define AK   5120           // K [64][80B]
#define AV   10240          // V [64][80B] row-major (trans-ldsm for PV)
#define ASA  15360          // fp32 S [49][64] = 12544
#define APB  0              // P bf16 [64][144B] overlays AQ/AK (9216 <= 10240)
#define PAIR_STRIDE 27904
#define ATTN_SMEM (2*PAIR_STRIDE)   // 55808

typedef unsigned long long ull;

// ---------------- scratch ----------------
__device__ __nv_bfloat16 g_xw  [(size_t)M_TOK * C_DIM];
__device__ __nv_bfloat16 g_qkv [(size_t)M_TOK * 3 * C_DIM];
__device__ __nv_bfloat16 g_att [(size_t)M_TOK * C_DIM];
__device__ float         g_x   [(size_t)M_TOK * C_DIM];
__device__ __nv_bfloat16 g_ln2 [(size_t)M_TOK * C_DIM];
__device__ __nv_bfloat16 g_h   [(size_t)M_TOK * HIDDEN];
__device__ __nv_bfloat16 g_wqkv[576 * 192];
__device__ __nv_bfloat16 g_wprj[192 * 192];
__device__ __nv_bfloat16 g_wfc1[768 * 192];
__device__ __nv_bfloat16 g_wfc2[192 * 768];

// ---------------- helpers ----------------
__device__ __forceinline__ uint32_t smem_u32(const void* p) {
    uint32_t a;
    asm("{ .reg .u64 t; cvta.to.shared.u64 t, %1; cvt.u32.u64 %0, t; }" : "=r"(a) : "l"(p));
    return a;
}
__device__ __forceinline__ void cp16(uint32_t sa, const void* g) {
    asm volatile("cp.async.cg.shared.global [%0], [%1], 16;" :: "r"(sa), "l"(g));
}
__device__ __forceinline__ void cp_commit() { asm volatile("cp.async.commit_group;"); }
template <int N>
__device__ __forceinline__ void cp_wait() { asm volatile("cp.async.wait_group %0;" :: "n"(N)); }

__device__ __forceinline__ void ldsm_x4(uint32_t* r, uint32_t addr) {
    asm volatile("ldmatrix.sync.aligned.m8n8.x4.shared.b16 {%0,%1,%2,%3}, [%4];"
        : "=r"(r[0]), "=r"(r[1]), "=r"(r[2]), "=r"(r[3]) : "r"(addr));
}
__device__ __forceinline__ void ldsm_x4_t(uint32_t* r, uint32_t addr) {
    asm volatile("ldmatrix.sync.aligned.m8n8.x4.trans.shared.b16 {%0,%1,%2,%3}, [%4];"
        : "=r"(r[0]), "=r"(r[1]), "=r"(r[2]), "=r"(r[3]) : "r"(addr));
}
__device__ __forceinline__ void mma16816(float* c, const uint32_t* a, const uint32_t* b) {
    asm volatile("mma.sync.aligned.m16n8k16.row.col.f32.bf16.bf16.f32 "
        "{%0,%1,%2,%3}, {%4,%5,%6,%7}, {%8,%9}, {%0,%1,%2,%3};"
        : "+f"(c[0]), "+f"(c[1]), "+f"(c[2]), "+f"(c[3])
        : "r"(a[0]), "r"(a[1]), "r"(a[2]), "r"(a[3]), "r"(b[0]), "r"(b[1]));
}
__device__ __forceinline__ float gelu_exact(float v) {
    return 0.5f * v * (1.0f + erff(v * 0.70710678118654752f));
}
__device__ __forceinline__ float warp_sum(float v) {
#pragma unroll
    for (int o = 16; o > 0; o >>= 1) v += __shfl_xor_sync(0xffffffffu, v, o);
    return v;
}
__device__ __forceinline__ float warp_max(float v) {
#pragma unroll
    for (int o = 16; o > 0; o >>= 1) v = fmaxf(v, __shfl_xor_sync(0xffffffffu, v, o));
    return v;
}
__device__ __forceinline__ int scatter_dst(int row) {
    int w = row / 49, n = row % 49;
    int bb = w >> 8, rr = w & 255;
    int wi = rr >> 4, wj = rr & 15;
    int i = n / 7, j = n % 7;
    int hh = wi * 7 + i + 3; if (hh >= 112) hh -= 112;
    int ww = wj * 7 + j + 3; if (ww >= 112) ww -= 112;
    return bb * 12544 + hh * 112 + ww;
}

// ---------------- combined weight transpose ----------------
__global__ void wprep_all(const float* __restrict__ Wq, const float* __restrict__ Wp,
                          const float* __restrict__ W1, const float* __restrict__ W2,
                          __nv_bfloat16* __restrict__ Tq, __nv_bfloat16* __restrict__ Tp,
                          __nv_bfloat16* __restrict__ T1, __nv_bfloat16* __restrict__ T2) {
    int i = blockIdx.x * 256 + threadIdx.x;
    if (i < 110592) {
        int k = i / 576, n = i % 576;
        Tq[(size_t)n * 192 + k] = __float2bfloat16(Wq[i]);
    } else if (i < 147456) {
        int j = i - 110592;
        int k = j / 192, n = j % 192;
        Tp[(size_t)n * 192 + k] = __float2bfloat16(Wp[j]);
    } else if (i < 294912) {
        int j = i - 147456;
        int k = j / 768, n = j % 768;
        T1[(size_t)n * 192 + k] = __float2bfloat16(W1[j]);
    } else if (i < 442368) {
        int j = i - 294912;
        int k = j / 192, n = j % 192;
        T2[(size_t)n * 768 + k] = __float2bfloat16(W2[j]);
    }
}

// ---------------- LayerNorm (gather variant, for LN1 only) ----------------
template <bool GATHER>
__global__ void ln_kernel(const float* __restrict__ in,
                          const float* __restrict__ gamma, const float* __restrict__ beta,
                          __nv_bfloat16* __restrict__ oh) {
    int t = blockIdx.x, c = threadIdx.x;
    int src = GATHER ? scatter_dst(t) : t;
    float v = in[(size_t)src * C_DIM + c];
    __shared__ float s1[6], s2[6];
    int wid = c >> 5, lid = c & 31;
    float s = warp_sum(v);
    if (lid == 0) s1[wid] = s;
    __syncthreads();
    float mean = (s1[0] + s1[1] + s1[2] + s1[3] + s1[4] + s1[5]) * (1.0f / 192.0f);
    float d = v - mean;
    float sq = warp_sum(d * d);
    if (lid == 0) s2[wid] = sq;
    __syncthreads();
    float var = (s2[0] + s2[1] + s2[2] + s2[3] + s2[4] + s2[5]) * (1.0f / 192.0f);
    float o = d * rsqrtf(var + 1e-5f) * gamma[c] + beta[c];
    oh[(size_t)t * C_DIM + c] = __float2bfloat16(o);
}

enum { EPI_BF16 = 0, EPI_GELU = 1, EPI_SCATTER = 2, EPI_RES = 3 };

// ---------------- GEMM-64: CTA 128x64 ----------------
template <int EPI>
__global__ __launch_bounds__(256, 2)
void gemm_mma(const __nv_bfloat16* __restrict__ Aact,
              const __nv_bfloat16* __restrict__ Bw,
              const float* __restrict__ bias, const float* __restrict__ res,
              float* __restrict__ outf, __nv_bfloat16* __restrict__ outb,
              int K, int Nout) {
    extern __shared__ __align__(16) char smem[];
    int tid = threadIdx.x;
    int wid = tid >> 5, lid = tid & 31;
    int wm = wid & 3, wn = wid >> 2;
    int mBase = blockIdx.y * BM;
    int nBase = blockIdx.x * BN;
    uint32_t sb = smem_u32(smem);

    float acc[2][4][4];
#pragma unroll
    for (int a = 0; a < 2; a++)
#pragma unroll
        for (int b = 0; b < 4; b++)
#pragma unroll
            for (int c = 0; c < 4; c++) acc[a][b][c] = 0.0f;

    int nch = K / BK;

    auto issue = [&](int c) {
        uint32_t sbase = sb + (c % NSTAGE) * STAGE_BYTES;
        int k0 = c * BK;
#pragma unroll
        for (int u = 0; u < 3; u++) {
            int ch = tid + u * 256;
            if (ch < 512) {
                int r = ch >> 2, cc = ch & 3;
                cp16(sbase + OFF_A + r * RPB + cc * 16,
                     Aact + (size_t)(mBase + r) * K + k0 + cc * 8);
            } else {
                int q = ch - 512, r = q >> 2, cc = q & 3;
                cp16(sbase + OFF_B + r * RPB + cc * 16,
                     Bw + (size_t)(nBase + r) * K + k0 + cc * 8);
            }
        }
        cp_commit();
    };

    int aRow = wm * 32 + (lid & 7) + ((lid >> 3) & 1) * 8;
    int aKof = (lid >> 4) * 16;
    int bRow = wn * 32 + (lid & 7) + ((lid >> 4) & 1) * 8;
    int bKof = ((lid >> 3) & 1) * 16;

    issue(0);
    if (nch > 1) issue(1);
    if (nch > 2) issue(2);
    for (int c = 0; c < nch; c++) {
        int rem = nch - 1 - c;
        if (c + 3 < nch) issue(c + 3);
        if (rem >= 3)      cp_wait<3>();
        else if (rem == 2) cp_wait<2>();
        else if (rem == 1) cp_wait<1>();
        else               cp_wait<0>();
        __syncthreads();

        uint32_t buf = sb + (c % NSTAGE) * STAGE_BYTES;
#pragma unroll
        for (int kb = 0; kb < 64; kb += 32) {
            uint32_t ahf[2][4], bhf[2][4];
#pragma unroll
            for (int mt = 0; mt < 2; mt++)
                ldsm_x4(ahf[mt], buf + OFF_A + (aRow + mt * 16) * RPB + kb + aKof);
#pragma unroll
            for (int half = 0; half < 2; half++)
                ldsm_x4(bhf[half], buf + OFF_B + (bRow + half * 16) * RPB + kb + bKof);
#pragma unroll
            for (int mt = 0; mt < 2; mt++)
#pragma unroll
                for (int nt = 0; nt < 4; nt++)
                    mma16816(acc[mt][nt], ahf[mt], bhf[nt >> 1] + (nt & 1) * 2);
        }
        __syncthreads();
    }

    int g = lid >> 2, tq = lid & 3;
#pragma unroll
    for (int mt = 0; mt < 2; mt++) {
#pragma unroll
        for (int half = 0; half < 2; half++) {
            int row = mBase + wm * 32 + mt * 16 + g + half * 8;
            int dst = (EPI == EPI_SCATTER) ? scatter_dst(row) : row;
#pragma unroll
            for (int nt = 0; nt < 4; nt++) {
                int col = nBase + wn * 32 + nt * 8 + tq * 2;
                float v0 = acc[mt][nt][half * 2 + 0] + bias[col];
                float v1 = acc[mt][nt][half * 2 + 1] + bias[col + 1];
                if (EPI == EPI_GELU) {
                    v0 = gelu_exact(v0); v1 = gelu_exact(v1);
                }
                if (EPI == EPI_GELU || EPI == EPI_BF16) {
                    __nv_bfloat162 hp;
                    hp.x = __float2bfloat16(v0); hp.y = __float2bfloat16(v1);
                    *(__nv_bfloat162*)(outb + (size_t)row * Nout + col) = hp;
                } else {
                    size_t o = (size_t)dst * Nout + col;
                    float2 rv = *(const float2*)(res + o);
                    float2 w; w.x = v0 + rv.x; w.y = v1 + rv.y;
                    *(float2*)(outf + o) = w;
                }
            }
        }
    }
}

// ---------------- GEMM-192: CTA 64x192, full-N (fc2: EPI_RES) ----------------
template <int EPI>
__global__ __launch_bounds__(256, 2)
void gemm_mma_n192(const __nv_bfloat16* __restrict__ Aact,
                   const __nv_bfloat16* __restrict__ Bw,
                   const float* __restrict__ bias, const float* __restrict__ res,
                   float* __restrict__ outf, int K) {
    extern __shared__ __align__(16) char smem[];
    const int Nout = 192;
    int tid = threadIdx.x;
    int wid = tid >> 5, lid = tid & 31;
    int wm = wid & 1, wn = wid >> 1;
    int mBase = blockIdx.y * BM2;
    uint32_t sb = smem_u32(smem);

    float acc[2][6][4];
#pragma unroll
    for (int a = 0; a < 2; a++)
#pragma unroll
        for (int b = 0; b < 6; b++)
#pragma unroll
            for (int c = 0; c < 4; c++) acc[a][b][c] = 0.0f;

    int nch = K / BK;

    auto issue = [&](int c) {
        uint32_t sbase = sb + (c % NSTAGE) * STAGE2;
        int k0 = c * BK;
#pragma unroll
        for (int u = 0; u < 4; u++) {
            int ch = tid + u * 256;
            if (ch < 256) {
                int r = ch >> 2, cc = ch & 3;
                cp16(sbase + r * RPB + cc * 16,
                     Aact + (size_t)(mBase + r) * K + k0 + cc * 8);
            } else {
                int q = ch - 256, r = q >> 2, cc = q & 3;
                cp16(sbase + OFF_B2 + r * RPB + cc * 16,
                     Bw + (size_t)r * K + k0 + cc * 8);
            }
        }
        cp_commit();
    };

    int aRow = wm * 32 + (lid & 7) + ((lid >> 3) & 1) * 8;
    int aKof = (lid >> 4) * 16;
    int bRow = wn * 48 + (lid & 7) + ((lid >> 4) & 1) * 8;
    int bKof = ((lid >> 3) & 1) * 16;

    issue(0);
    if (nch > 1) issue(1);
    if (nch > 2) issue(2);
    for (int c = 0; c < nch; c++) {
        int rem = nch - 1 - c;
        if (c + 3 < nch) issue(c + 3);
        if (rem >= 3)      cp_wait<3>();
        else if (rem == 2) cp_wait<2>();
        else if (rem == 1) cp_wait<1>();
        else               cp_wait<0>();
        __syncthreads();

        uint32_t buf = sb + (c % NSTAGE) * STAGE2;
#pragma unroll
        for (int kb = 0; kb < 64; kb += 32) {
            uint32_t ahf[2][4], bhf[3][4];
#pragma unroll
            for (int mt = 0; mt < 2; mt++)
                ldsm_x4(ahf[mt], buf + (aRow + mt * 16) * RPB + kb + aKof);
#pragma unroll
            for (int nb = 0; nb < 3; nb++)
                ldsm_x4(bhf[nb], buf + OFF_B2 + (bRow + nb * 16) * RPB + kb + bKof);
#pragma unroll
            for (int mt = 0; mt < 2; mt++)
#pragma unroll
                for (int nt = 0; nt < 6; nt++)
                    mma16816(acc[mt][nt], ahf[mt], bhf[nt >> 1] + (nt & 1) * 2);
        }
        __syncthreads();
    }

    int g = lid >> 2, tq = lid & 3;
#pragma unroll
    for (int mt = 0; mt < 2; mt++) {
#pragma unroll
        for (int half = 0; half < 2; half++) {
            int row = mBase + wm * 32 + mt * 16 + g + half * 8;
            int dst = (EPI == EPI_SCATTER) ? scatter_dst(row) : row;
#pragma unroll
            for (int nt = 0; nt < 6; nt++) {
                int col = wn * 48 + nt * 8 + tq * 2;
                float v0 = acc[mt][nt][half * 2 + 0] + bias[col];
                float v1 = acc[mt][nt][half * 2 + 1] + bias[col + 1];
                size_t o = (size_t)dst * Nout + col;
                float2 rv = *(const float2*)(res + o);
                float2 w; w.x = v0 + rv.x; w.y = v1 + rv.y;
                *(float2*)(outf + o) = w;
            }
        }
    }
}

// ---------------- proj GEMM + scatter + residual + fused LN2 ----------------
__global__ __launch_bounds__(256, 2)
void gemm_proj_ln(const __nv_bfloat16* __restrict__ Aact,
                  const __nv_bfloat16* __restrict__ Bw,
                  const float* __restrict__ bias, const float* __restrict__ res,
                  float* __restrict__ outx, __nv_bfloat16* __restrict__ outln,
                  const float* __restrict__ gamma, const float* __restrict__ beta,
                  int K) {
    extern __shared__ __align__(16) char smem[];
    const int Nout = 192;
    int tid = threadIdx.x;
    int wid = tid >> 5, lid = tid & 31;
    int wm = wid & 1, wn = wid >> 1;
    int mBase = blockIdx.y * BM2;
    uint32_t sb = smem_u32(smem);

    float acc[2][6][4];
#pragma unroll
    for (int a = 0; a < 2; a++)
#pragma unroll
        for (int b = 0; b < 6; b++)
#pragma unroll
            for (int c = 0; c < 4; c++) acc[a][b][c] = 0.0f;

    int nch = K / BK;

    auto issue = [&](int c) {
        uint32_t sbase = sb + (c % NSTAGE) * STAGE2;
        int k0 = c * BK;
#pragma unroll
        for (int u = 0; u < 4; u++) {
            int ch = tid + u * 256;
            if (ch < 256) {
                int r = ch >> 2, cc = ch & 3;
                cp16(sbase + r * RPB + cc * 16,
                     Aact + (size_t)(mBase + r) * K + k0 + cc * 8);
            } else {
                int q = ch - 256, r = q >> 2, cc = q & 3;
                cp16(sbase + OFF_B2 + r * RPB + cc * 16,
                     Bw + (size_t)r * K + k0 + cc * 8);
            }
        }
        cp_commit();
    };

    int aRow = wm * 32 + (lid & 7) + ((lid >> 3) & 1) * 8;
    int aKof = (lid >> 4) * 16;
    int bRow = wn * 48 + (lid & 7) + ((lid >> 4) & 1) * 8;
    int bKof = ((lid >> 3) & 1) * 16;

    issue(0);
    if (nch > 1) issue(1);
    if (nch > 2) issue(2);
    for (int c = 0; c < nch; c++) {
        int rem = nch - 1 - c;
        if (c + 3 < nch) issue(c + 3);
        if (rem >= 3)      cp_wait<3>();
        else if (rem == 2) cp_wait<2>();
        else if (rem == 1) cp_wait<1>();
        else               cp_wait<0>();
        __syncthreads();

        uint32_t buf = sb + (c % NSTAGE) * STAGE2;
#pragma unroll
        for (int kb = 0; kb < 64; kb += 32) {
            uint32_t ahf[2][4], bhf[3][4];
#pragma unroll
            for (int mt = 0; mt < 2; mt++)
                ldsm_x4(ahf[mt], buf + (aRow + mt * 16) * RPB + kb + aKof);
#pragma unroll
            for (int nb = 0; nb < 3; nb++)
                ldsm_x4(bhf[nb], buf + OFF_B2 + (bRow + nb * 16) * RPB + kb + bKof);
#pragma unroll
            for (int mt = 0; mt < 2; mt++)
#pragma unroll
                for (int nt = 0; nt < 6; nt++)
                    mma16816(acc[mt][nt], ahf[mt], bhf[nt >> 1] + (nt & 1) * 2);
        }
        __syncthreads();
    }

    // ---- epilogue: x = acc + bias + residual; write x; fused LN -> outln ----
    int g = lid >> 2, tq = lid & 3;
    int dsts[2][2];
    float psum[2][2], psq[2][2];
#pragma unroll
    for (int mt = 0; mt < 2; mt++) {
#pragma unroll
        for (int half = 0; half < 2; half++) {
            int row = mBase + wm * 32 + mt * 16 + g + half * 8;
            int dst = scatter_dst(row);
            dsts[mt][half] = dst;
            float s = 0.0f, sq = 0.0f;
#pragma unroll
            for (int nt = 0; nt < 6; nt++) {
                int col = wn * 48 + nt * 8 + tq * 2;
                size_t o = (size_t)dst * Nout + col;
                float2 rv = *(const float2*)(res + o);
                float v0 = acc[mt][nt][half * 2 + 0] + bias[col] + rv.x;
                float v1 = acc[mt][nt][half * 2 + 1] + bias[col + 1] + rv.y;
                acc[mt][nt][half * 2 + 0] = v0;
                acc[mt][nt][half * 2 + 1] = v1;
                float2 w; w.x = v0; w.y = v1;
                *(float2*)(outx + o) = w;
                s += v0 + v1;
                sq += v0 * v0 + v1 * v1;
            }
            // reduce over tq quad (4 lanes share the row within this warp)
            s  += __shfl_xor_sync(0xffffffffu, s, 1);
            s  += __shfl_xor_sync(0xffffffffu, s, 2);
            sq += __shfl_xor_sync(0xffffffffu, sq, 1);
            sq += __shfl_xor_sync(0xffffffffu, sq, 2);
            psum[mt][half] = s;
            psq[mt][half] = sq;
        }
    }
    // cross-warp (4 wn warps per row) partial exchange via smem
    float2* part = (float2*)smem;   // [64 rows][4 wn]
    __syncthreads();
#pragma unroll
    for (int mt = 0; mt < 2; mt++)
#pragma unroll
        for (int half = 0; half < 2; half++) {
            int rloc = wm * 32 + mt * 16 + g + half * 8;
            if (tq == 0) part[rloc * 4 + wn] = make_float2(psum[mt][half], psq[mt][half]);
        }
    __syncthreads();
#pragma unroll
    for (int mt = 0; mt < 2; mt++) {
#pragma unroll
        for (int half = 0; half < 2; half++) {
            int rloc = wm * 32 + mt * 16 + g + half * 8;
            float2 p0 = part[rloc * 4 + 0], p1 = part[rloc * 4 + 1];
            float2 p2 = part[rloc * 4 + 2], p3 = part[rloc * 4 + 3];
            float s = p0.x + p1.x + p2.x + p3.x;
            float sq = p0.y + p1.y + p2.y + p3.y;
            float mean = s * (1.0f / 192.0f);
            float var = sq * (1.0f / 192.0f) - mean * mean;
            float rstd = rsqrtf(var + 1e-5f);
            int dst = dsts[mt][half];
#pragma unroll
            for (int nt = 0; nt < 6; nt++) {
                int col = wn * 48 + nt * 8 + tq * 2;
                float v0 = (acc[mt][nt][half * 2 + 0] - mean) * rstd * gamma[col] + beta[col];
                float v1 = (acc[mt][nt][half * 2 + 1] - mean) * rstd * gamma[col + 1] + beta[col + 1];
                __nv_bfloat162 hp;
                hp.x = __float2bfloat16(v0); hp.y = __float2bfloat16(v1);
                *(__nv_bfloat162*)(outln + (size_t)dst * Nout + col) = hp;
            }
        }
    }
}

// ---------------- Windowed attention (mma.sync, trans-ldsm V, vectorized IO) ----------------
__global__ __launch_bounds__(256)
void attn_kernel(const __nv_bfloat16* __restrict__ qkv,
                 const float* __restrict__ rpb,
                 __nv_bfloat16* __restrict__ oh) {
    extern __shared__ __align__(16) char smem[];
    __shared__ int Ls[49];
    __shared__ int Rs[2][49];

    int tid = threadIdx.x;
    int wid = tid >> 5, lid = tid & 31;
    int ph = wid >> 2;
    int t  = wid & 3;
    int wtid = tid & 127;
    int pair = blockIdx.x * 2 + ph;
    int w = pair / NHEADS;
    int h = pair - w * NHEADS;

    char* sm = smem + ph * PAIR_STRIDE;
    uint32_t sb = smem_u32(smem) + ph * PAIR_STRIDE;
    const float scale = 0.17677669529663687f;

    int r = w & 255;
    int wi = r >> 4, wj = r & 15;

    if (tid < 49) Ls[tid] = 13 * (tid / 7) + tid % 7;
    if (wtid < 49) {
        int i = wtid / 7, j = wtid % 7;
        int hp = wi * 7 + i, wp = wj * 7 + j;
        Rs[ph][wtid] = (hp < 105 ? 0 : (hp < 109 ? 1 : 2)) * 3 + (wp < 105 ? 0 : (wp < 109 ? 1 : 2));
    }

    // vectorized loads: Q,K,V all row-major [n][d] pitch 80, uint4 stores
    for (int idx = wtid; idx < 196; idx += 128) {
        int n = idx >> 2, c = idx & 3;
        size_t base = ((size_t)(w * 49 + n)) * (3 * C_DIM) + h * HDIM + c * 8;
        *(uint4*)(sm + AQ + n * 80 + c * 16) = *(const uint4*)(qkv + base);
        *(uint4*)(sm + AK + n * 80 + c * 16) = *(const uint4*)(qkv + base + C_DIM);
        *(uint4*)(sm + AV + n * 80 + c * 16) = *(const uint4*)(qkv + base + 2 * C_DIM);
    }
    // zero V rows m=49..63 (P pad cols are 0 but 0*NaN = NaN)
    for (int idx = wtid; idx < 60; idx += 128) {
        int n = 49 + idx / 4, c = idx & 3;
        *(uint4*)(sm + AV + n * 80 + c * 16) = make_uint4(0, 0, 0, 0);
    }
    __syncthreads();

    int aRow = t * 16 + (lid & 7) + ((lid >> 3) & 1) * 8;
    int aKof = (lid >> 4) * 16;
    int bRowB = (lid & 7) + ((lid >> 4) & 1) * 8;
    int bKof = ((lid >> 3) & 1) * 16;
    // trans-ldsm lane mapping for V [m][d]: row = k(m) index, col-byte = d half
    int vRow = (lid & 7) + ((lid >> 3) & 1) * 8;
    int vCol = ((lid >> 4) & 1) * 16;
    int g = lid >> 2, tq = lid & 3;

    // ---- S = Q K^T (64x64x32) ----
    {
        float acc[8][4];
#pragma unroll
        for (int a = 0; a < 8; a++)
#pragma unroll
            for (int c = 0; c < 4; c++) acc[a][c] = 0.0f;
#pragma unroll
        for (int kb = 0; kb < 64; kb += 32) {
            uint32_t af[4];
            ldsm_x4(af, sb + AQ + aRow * 80 + kb + aKof);
#pragma unroll
            for (int nb = 0; nb < 4; nb++) {
                uint32_t bf[4];
                ldsm_x4(bf, sb + AK + (bRowB + nb * 16) * 80 + kb + bKof);
                mma16816(acc[2 * nb],     af, bf);
                mma16816(acc[2 * nb + 1], af, bf + 2);
            }
        }
        float* sa = (float*)(sm + ASA);
#pragma unroll
        for (int half = 0; half < 2; half++) {
            int row = t * 16 + g + half * 8;
            if (row < 49) {
                int L0 = Ls[row] + 84, R0 = Rs[ph][row];
#pragma unroll
                for (int nt = 0; nt < 8; nt++) {
                    int col = nt * 8 + tq * 2;
                    if (col < 49) {
#pragma unroll
                        for (int e = 0; e < 2; e++) {
                            int cc = col + e;
                            if (cc < 49) {
                                float vs = acc[nt][half * 2 + e] * scale
                                         + rpb[(L0 - Ls[cc]) * NHEADS + h]
                                         + (R0 == Rs[ph][cc] ? 0.0f : -100.0f);
                                sa[row * 64 + cc] = vs;
                            }
                        }
                    }
                }
            }
        }
    }
    __syncthreads();

    // ---- softmax rows; normalized bf16 P directly into APB ----
    {
        float* sa = (float*)(sm + ASA);
        char* pb = sm + APB;
        for (int n = t; n < 49; n += 4) {
            float v1 = sa[n * 64 + lid];
            float v2 = (lid < 17) ? sa[n * 64 + 32 + lid] : -1e30f;
            float mx = warp_max(fmaxf(v1, v2));
            float e1 = __expf(v1 - mx);
            float e2 = (lid < 17) ? __expf(v2 - mx) : 0.0f;
            float s = warp_sum(e1 + e2);
            float inv = 1.0f / s;
            *(__nv_bfloat16*)(pb + n * 144 + lid * 2) = __float2bfloat16(e1 * inv);
            *(__nv_bfloat16*)(pb + n * 144 + (lid + 32) * 2) =
                __float2bfloat16(lid < 17 ? e2 * inv : 0.0f);
        }
        for (int idx = wtid; idx < 120; idx += 128) {
            int n = 49 + (idx >> 3), c = idx & 7;
            *(uint4*)(pb + n * 144 + c * 16) = make_uint4(0, 0, 0, 0);
        }
    }
    __syncthreads();

    // ---- O = P V (64x32x64), V via trans-ldsm from row-major [m][d] ----
    {
        float acc[4][4];
#pragma unroll
        for (int a = 0; a < 4; a++)
#pragma unroll
            for (int c = 0; c < 4; c++) acc[a][c] = 0.0f;
#pragma unroll
        for (int ks = 0; ks < 4; ks++) {
            int kb = ks * 32;
            uint32_t af[4];
            ldsm_x4(af, sb + APB + aRow * 144 + kb + aKof);
            uint32_t bf0[4], bf1[4];
            uint32_t vbase = sb + AV + (ks * 16 + vRow) * 80 + vCol;
            ldsm_x4_t(bf0, vbase);          // d 0..15
            ldsm_x4_t(bf1, vbase + 32);     // d 16..31
            mma16816(acc[0], af, bf0);
            mma16816(acc[1], af, bf0 + 2);
            mma16816(acc[2], af, bf1);
            mma16816(acc[3], af, bf1 + 2);
        }
#pragma unroll
        for (int half = 0; half < 2; half++) {
            int row = t * 16 + g + half * 8;
            if (row < 49) {
#pragma unroll
                for (int nt = 0; nt < 4; nt++) {
                    int col = nt * 8 + tq * 2;
                    __nv_bfloat162 hp;
                    hp.x = __float2bfloat16(acc[nt][half * 2 + 0]);
                    hp.y = __float2bfloat16(acc[nt][half * 2 + 1]);
                    size_t o = ((size_t)(w * 49 + row)) * C_DIM + h * HDIM + col;
                    *(__nv_bfloat162*)(oh + o) = hp;
                }
            }
        }
    }
}

// ---------------- launch ----------------
extern "C" void kernel_launch(void* const* d_in, const int* in_sizes, int n_in,
                              void* d_out, int out_size) {
    const float* query   = (const float*)d_in[0];
    const float* norm1_g = (const float*)d_in[1];
    const float* norm1_b = (const float*)d_in[2];
    const float* qkv_w   = (const float*)d_in[3];
    const float* qkv_b   = (const float*)d_in[4];
    const float* rpb     = (const float*)d_in[5];
    const float* proj_w  = (const float*)d_in[6];
    const float* proj_b  = (const float*)d_in[7];
    const float* norm2_g = (const float*)d_in[8];
    const float* norm2_b = (const float*)d_in[9];
    const float* fc1_w   = (const float*)d_in[10];
    const float* fc1_b   = (const float*)d_in[11];
    const float* fc2_w   = (const float*)d_in[12];
    const float* fc2_b   = (const float*)d_in[13];
    float* out = (float*)d_out;

    __nv_bfloat16 *xw, *qkvp, *att, *ln2, *hbuf;
    __nv_bfloat16 *wq, *wp, *w1, *w2;
    float *x;
    cudaGetSymbolAddress((void**)&xw, g_xw);
    cudaGetSymbolAddress((void**)&qkvp, g_qkv);
    cudaGetSymbolAddress((void**)&att, g_att);
    cudaGetSymbolAddress((void**)&x, g_x);
    cudaGetSymbolAddress((void**)&ln2, g_ln2);
    cudaGetSymbolAddress((void**)&hbuf, g_h);
    cudaGetSymbolAddress((void**)&wq, g_wqkv);
    cudaGetSymbolAddress((void**)&wp, g_wprj);
    cudaGetSymbolAddress((void**)&w1, g_wfc1);
    cudaGetSymbolAddress((void**)&w2, g_wfc2);

    const int SMEM  = NSTAGE * STAGE_BYTES;  // 61440
    const int SMEM2 = NSTAGE * STAGE2;       // 81920
    cudaFuncSetAttribute(gemm_mma<EPI_BF16>, cudaFuncAttributeMaxDynamicSharedMemorySize, SMEM);
    cudaFuncSetAttribute(gemm_mma<EPI_GELU>, cudaFuncAttributeMaxDynamicSharedMemorySize, SMEM);
    cudaFuncSetAttribute(gemm_proj_ln,       cudaFuncAttributeMaxDynamicSharedMemorySize, SMEM2);
    cudaFuncSetAttribute(gemm_mma_n192<EPI_RES>, cudaFuncAttributeMaxDynamicSharedMemorySize, SMEM2);
    cudaFuncSetAttribute(attn_kernel, cudaFuncAttributeMaxDynamicSharedMemorySize, ATTN_SMEM);

    wprep_all<<<(442368 + 255) / 256, 256>>>(qkv_w, proj_w, fc1_w, fc2_w, wq, wp, w1, w2);

    // 1) LN1 + shift + window partition
    ln_kernel<true><<<M_TOK, 192>>>(query, norm1_g, norm1_b, xw);

    // 2) qkv  [100352,192] x [192,576] -> bf16
    gemm_mma<EPI_BF16><<<dim3(576 / BN, M_TOK / BM), 256, SMEM>>>(
        xw, wq, qkv_b, nullptr, nullptr, qkvp, 192, 576);

    // 3) windowed attention
    attn_kernel<<<2048 * NHEADS / 2, 256, ATTN_SMEM>>>(qkvp, rpb, att);

    // 4) proj + window reverse + unshift + residual(query) + fused LN2
    gemm_proj_ln<<<dim3(1, M_TOK / BM2), 256, SMEM2>>>(
        att, wp, proj_b, query, x, ln2, norm2_g, norm2_b, 192);

    // 5) fc1 + GELU
    gemm_mma<EPI_GELU><<<dim3(768 / BN, M_TOK / BM), 256, SMEM>>>(
        ln2, w1, fc1_b, nullptr, nullptr, hbuf, 192, 768);

    // 6) fc2 + residual(x) -> out
    gemm_mma_n192<EPI_RES><<<dim3(1, M_TOK / BM2), 256, SMEM2>>>(
        hbuf, w2, fc2_b, x, out, 768);
}

// round 17
// speedup vs baseline: 1.0808x; 1.0808x over previous
#include <cuda_runtime.h>
#include <cuda_bf16.h>
#include <math.h>
#include <stdint.h>

#define M_TOK   100352
#define C_DIM   192
#define NHEADS  6
#define HDIM    32
#define HIDDEN  768

// GEMM-64 tiling
#define BM 128
#define BN 64
#define BK 32
#define RPB 80
#define OFF_A  0
#define OFF_B  (BM*RPB)
#define STAGE_BYTES (BM*RPB + BN*RPB)
#define NSTAGE 4
// GEMM-192 tiling
#define BM2 64
#define BN2 192
#define OFF_B2 (BM2*RPB)
#define STAGE2 (BM2*RPB + BN2*RPB)

// attention smem layout (per pair) — register softmax, no fp32 S buffer
#define AQ   0              // Q [64][80B]
#define AK   5120           // K [64][80B]
#define AV   10240          // V [64][80B] row-major (trans-ldsm for PV)
#define APB  0              // P bf16 [64][144B] overlays AQ/AK (9216 <= 10240)
#define PAIR_STRIDE 15360
#define ATTN_SMEM (2*PAIR_STRIDE)   // 30720

typedef unsigned long long ull;

// ---------------- scratch ----------------
__device__ __nv_bfloat16 g_xw  [(size_t)M_TOK * C_DIM];
__device__ __nv_bfloat16 g_qkv [(size_t)M_TOK * 3 * C_DIM];
__device__ __nv_bfloat16 g_att [(size_t)M_TOK * C_DIM];
__device__ float         g_x   [(size_t)M_TOK * C_DIM];
__device__ __nv_bfloat16 g_ln2 [(size_t)M_TOK * C_DIM];
__device__ __nv_bfloat16 g_h   [(size_t)M_TOK * HIDDEN];
__device__ __nv_bfloat16 g_wqkv[576 * 192];
__device__ __nv_bfloat16 g_wprj[192 * 192];
__device__ __nv_bfloat16 g_wfc1[768 * 192];
__device__ __nv_bfloat16 g_wfc2[192 * 768];

// ---------------- helpers ----------------
__device__ __forceinline__ uint32_t smem_u32(const void* p) {
    uint32_t a;
    asm("{ .reg .u64 t; cvta.to.shared.u64 t, %1; cvt.u32.u64 %0, t; }" : "=r"(a) : "l"(p));
    return a;
}
__device__ __forceinline__ void cp16(uint32_t sa, const void* g) {
    asm volatile("cp.async.cg.shared.global [%0], [%1], 16;" :: "r"(sa), "l"(g));
}
__device__ __forceinline__ void cp_commit() { asm volatile("cp.async.commit_group;"); }
template <int N>
__device__ __forceinline__ void cp_wait() { asm volatile("cp.async.wait_group %0;" :: "n"(N)); }

__device__ __forceinline__ void ldsm_x4(uint32_t* r, uint32_t addr) {
    asm volatile("ldmatrix.sync.aligned.m8n8.x4.shared.b16 {%0,%1,%2,%3}, [%4];"
        : "=r"(r[0]), "=r"(r[1]), "=r"(r[2]), "=r"(r[3]) : "r"(addr));
}
__device__ __forceinline__ void ldsm_x4_t(uint32_t* r, uint32_t addr) {
    asm volatile("ldmatrix.sync.aligned.m8n8.x4.trans.shared.b16 {%0,%1,%2,%3}, [%4];"
        : "=r"(r[0]), "=r"(r[1]), "=r"(r[2]), "=r"(r[3]) : "r"(addr));
}
__device__ __forceinline__ void mma16816(float* c, const uint32_t* a, const uint32_t* b) {
    asm volatile("mma.sync.aligned.m16n8k16.row.col.f32.bf16.bf16.f32 "
        "{%0,%1,%2,%3}, {%4,%5,%6,%7}, {%8,%9}, {%0,%1,%2,%3};"
        : "+f"(c[0]), "+f"(c[1]), "+f"(c[2]), "+f"(c[3])
        : "r"(a[0]), "r"(a[1]), "r"(a[2]), "r"(a[3]), "r"(b[0]), "r"(b[1]));
}
__device__ __forceinline__ float gelu_exact(float v) {
    return 0.5f * v * (1.0f + erff(v * 0.70710678118654752f));
}
__device__ __forceinline__ float warp_sum(float v) {
#pragma unroll
    for (int o = 16; o > 0; o >>= 1) v += __shfl_xor_sync(0xffffffffu, v, o);
    return v;
}
__device__ __forceinline__ float warp_max(float v) {
#pragma unroll
    for (int o = 16; o > 0; o >>= 1) v = fmaxf(v, __shfl_xor_sync(0xffffffffu, v, o));
    return v;
}
__device__ __forceinline__ int scatter_dst(int row) {
    int w = row / 49, n = row % 49;
    int bb = w >> 8, rr = w & 255;
    int wi = rr >> 4, wj = rr & 15;
    int i = n / 7, j = n % 7;
    int hh = wi * 7 + i + 3; if (hh >= 112) hh -= 112;
    int ww = wj * 7 + j + 3; if (ww >= 112) ww -= 112;
    return bb * 12544 + hh * 112 + ww;
}

// ---------------- combined weight transpose ----------------
__global__ void wprep_all(const float* __restrict__ Wq, const float* __restrict__ Wp,
                          const float* __restrict__ W1, const float* __restrict__ W2,
                          __nv_bfloat16* __restrict__ Tq, __nv_bfloat16* __restrict__ Tp,
                          __nv_bfloat16* __restrict__ T1, __nv_bfloat16* __restrict__ T2) {
    int i = blockIdx.x * 256 + threadIdx.x;
    if (i < 110592) {
        int k = i / 576, n = i % 576;
        Tq[(size_t)n * 192 + k] = __float2bfloat16(Wq[i]);
    } else if (i < 147456) {
        int j = i - 110592;
        int k = j / 192, n = j % 192;
        Tp[(size_t)n * 192 + k] = __float2bfloat16(Wp[j]);
    } else if (i < 294912) {
        int j = i - 147456;
        int k = j / 768, n = j % 768;
        T1[(size_t)n * 192 + k] = __float2bfloat16(W1[j]);
    } else if (i < 442368) {
        int j = i - 294912;
        int k = j / 192, n = j % 192;
        T2[(size_t)n * 768 + k] = __float2bfloat16(W2[j]);
    }
}

// ---------------- LayerNorm (gather variant, for LN1 only) ----------------
template <bool GATHER>
__global__ void ln_kernel(const float* __restrict__ in,
                          const float* __restrict__ gamma, const float* __restrict__ beta,
                          __nv_bfloat16* __restrict__ oh) {
    int t = blockIdx.x, c = threadIdx.x;
    int src = GATHER ? scatter_dst(t) : t;
    float v = in[(size_t)src * C_DIM + c];
    __shared__ float s1[6], s2[6];
    int wid = c >> 5, lid = c & 31;
    float s = warp_sum(v);
    if (lid == 0) s1[wid] = s;
    __syncthreads();
    float mean = (s1[0] + s1[1] + s1[2] + s1[3] + s1[4] + s1[5]) * (1.0f / 192.0f);
    float d = v - mean;
    float sq = warp_sum(d * d);
    if (lid == 0) s2[wid] = sq;
    __syncthreads();
    float var = (s2[0] + s2[1] + s2[2] + s2[3] + s2[4] + s2[5]) * (1.0f / 192.0f);
    float o = d * rsqrtf(var + 1e-5f) * gamma[c] + beta[c];
    oh[(size_t)t * C_DIM + c] = __float2bfloat16(o);
}

enum { EPI_BF16 = 0, EPI_GELU = 1, EPI_SCATTER = 2, EPI_RES = 3 };

// ---------------- GEMM-64: CTA 128x64 ----------------
template <int EPI>
__global__ __launch_bounds__(256, 2)
void gemm_mma(const __nv_bfloat16* __restrict__ Aact,
              const __nv_bfloat16* __restrict__ Bw,
              const float* __restrict__ bias, const float* __restrict__ res,
              float* __restrict__ outf, __nv_bfloat16* __restrict__ outb,
              int K, int Nout) {
    extern __shared__ __align__(16) char smem[];
    int tid = threadIdx.x;
    int wid = tid >> 5, lid = tid & 31;
    int wm = wid & 3, wn = wid >> 2;
    int mBase = blockIdx.y * BM;
    int nBase = blockIdx.x * BN;
    uint32_t sb = smem_u32(smem);

    float acc[2][4][4];
#pragma unroll
    for (int a = 0; a < 2; a++)
#pragma unroll
        for (int b = 0; b < 4; b++)
#pragma unroll
            for (int c = 0; c < 4; c++) acc[a][b][c] = 0.0f;

    int nch = K / BK;

    auto issue = [&](int c) {
        uint32_t sbase = sb + (c % NSTAGE) * STAGE_BYTES;
        int k0 = c * BK;
#pragma unroll
        for (int u = 0; u < 3; u++) {
            int ch = tid + u * 256;
            if (ch < 512) {
                int r = ch >> 2, cc = ch & 3;
                cp16(sbase + OFF_A + r * RPB + cc * 16,
                     Aact + (size_t)(mBase + r) * K + k0 + cc * 8);
            } else {
                int q = ch - 512, r = q >> 2, cc = q & 3;
                cp16(sbase + OFF_B + r * RPB + cc * 16,
                     Bw + (size_t)(nBase + r) * K + k0 + cc * 8);
            }
        }
        cp_commit();
    };

    int aRow = wm * 32 + (lid & 7) + ((lid >> 3) & 1) * 8;
    int aKof = (lid >> 4) * 16;
    int bRow = wn * 32 + (lid & 7) + ((lid >> 4) & 1) * 8;
    int bKof = ((lid >> 3) & 1) * 16;

    issue(0);
    if (nch > 1) issue(1);
    if (nch > 2) issue(2);
    for (int c = 0; c < nch; c++) {
        int rem = nch - 1 - c;
        if (c + 3 < nch) issue(c + 3);
        if (rem >= 3)      cp_wait<3>();
        else if (rem == 2) cp_wait<2>();
        else if (rem == 1) cp_wait<1>();
        else               cp_wait<0>();
        __syncthreads();

        uint32_t buf = sb + (c % NSTAGE) * STAGE_BYTES;
#pragma unroll
        for (int kb = 0; kb < 64; kb += 32) {
            uint32_t ahf[2][4], bhf[2][4];
#pragma unroll
            for (int mt = 0; mt < 2; mt++)
                ldsm_x4(ahf[mt], buf + OFF_A + (aRow + mt * 16) * RPB + kb + aKof);
#pragma unroll
            for (int half = 0; half < 2; half++)
                ldsm_x4(bhf[half], buf + OFF_B + (bRow + half * 16) * RPB + kb + bKof);
#pragma unroll
            for (int mt = 0; mt < 2; mt++)
#pragma unroll
                for (int nt = 0; nt < 4; nt++)
                    mma16816(acc[mt][nt], ahf[mt], bhf[nt >> 1] + (nt & 1) * 2);
        }
        __syncthreads();
    }

    int g = lid >> 2, tq = lid & 3;
#pragma unroll
    for (int mt = 0; mt < 2; mt++) {
#pragma unroll
        for (int half = 0; half < 2; half++) {
            int row = mBase + wm * 32 + mt * 16 + g + half * 8;
            int dst = (EPI == EPI_SCATTER) ? scatter_dst(row) : row;
#pragma unroll
            for (int nt = 0; nt < 4; nt++) {
                int col = nBase + wn * 32 + nt * 8 + tq * 2;
                float v0 = acc[mt][nt][half * 2 + 0] + bias[col];
                float v1 = acc[mt][nt][half * 2 + 1] + bias[col + 1];
                if (EPI == EPI_GELU) {
                    v0 = gelu_exact(v0); v1 = gelu_exact(v1);
                }
                if (EPI == EPI_GELU || EPI == EPI_BF16) {
                    __nv_bfloat162 hp;
                    hp.x = __float2bfloat16(v0); hp.y = __float2bfloat16(v1);
                    *(__nv_bfloat162*)(outb + (size_t)row * Nout + col) = hp;
                } else {
                    size_t o = (size_t)dst * Nout + col;
                    float2 rv = *(const float2*)(res + o);
                    float2 w; w.x = v0 + rv.x; w.y = v1 + rv.y;
                    *(float2*)(outf + o) = w;
                }
            }
        }
    }
}

// ---------------- GEMM-192: CTA 64x192, full-N (fc2: EPI_RES) ----------------
template <int EPI>
__global__ __launch_bounds__(256, 2)
void gemm_mma_n192(const __nv_bfloat16* __restrict__ Aact,
                   const __nv_bfloat16* __restrict__ Bw,
                   const float* __restrict__ bias, const float* __restrict__ res,
                   float* __restrict__ outf, int K) {
    extern __shared__ __align__(16) char smem[];
    const int Nout = 192;
    int tid = threadIdx.x;
    int wid = tid >> 5, lid = tid & 31;
    int wm = wid & 1, wn = wid >> 1;
    int mBase = blockIdx.y * BM2;
    uint32_t sb = smem_u32(smem);

    float acc[2][6][4];
#pragma unroll
    for (int a = 0; a < 2; a++)
#pragma unroll
        for (int b = 0; b < 6; b++)
#pragma unroll
            for (int c = 0; c < 4; c++) acc[a][b][c] = 0.0f;

    int nch = K / BK;

    auto issue = [&](int c) {
        uint32_t sbase = sb + (c % NSTAGE) * STAGE2;
        int k0 = c * BK;
#pragma unroll
        for (int u = 0; u < 4; u++) {
            int ch = tid + u * 256;
            if (ch < 256) {
                int r = ch >> 2, cc = ch & 3;
                cp16(sbase + r * RPB + cc * 16,
                     Aact + (size_t)(mBase + r) * K + k0 + cc * 8);
            } else {
                int q = ch - 256, r = q >> 2, cc = q & 3;
                cp16(sbase + OFF_B2 + r * RPB + cc * 16,
                     Bw + (size_t)r * K + k0 + cc * 8);
            }
        }
        cp_commit();
    };

    int aRow = wm * 32 + (lid & 7) + ((lid >> 3) & 1) * 8;
    int aKof = (lid >> 4) * 16;
    int bRow = wn * 48 + (lid & 7) + ((lid >> 4) & 1) * 8;
    int bKof = ((lid >> 3) & 1) * 16;

    issue(0);
    if (nch > 1) issue(1);
    if (nch > 2) issue(2);
    for (int c = 0; c < nch; c++) {
        int rem = nch - 1 - c;
        if (c + 3 < nch) issue(c + 3);
        if (rem >= 3)      cp_wait<3>();
        else if (rem == 2) cp_wait<2>();
        else if (rem == 1) cp_wait<1>();
        else               cp_wait<0>();
        __syncthreads();

        uint32_t buf = sb + (c % NSTAGE) * STAGE2;
#pragma unroll
        for (int kb = 0; kb < 64; kb += 32) {
            uint32_t ahf[2][4], bhf[3][4];
#pragma unroll
            for (int mt = 0; mt < 2; mt++)
                ldsm_x4(ahf[mt], buf + (aRow + mt * 16) * RPB + kb + aKof);
#pragma unroll
            for (int nb = 0; nb < 3; nb++)
                ldsm_x4(bhf[nb], buf + OFF_B2 + (bRow + nb * 16) * RPB + kb + bKof);
#pragma unroll
            for (int mt = 0; mt < 2; mt++)
#pragma unroll
                for (int nt = 0; nt < 6; nt++)
                    mma16816(acc[mt][nt], ahf[mt], bhf[nt >> 1] + (nt & 1) * 2);
        }
        __syncthreads();
    }

    int g = lid >> 2, tq = lid & 3;
#pragma unroll
    for (int mt = 0; mt < 2; mt++) {
#pragma unroll
        for (int half = 0; half < 2; half++) {
            int row = mBase + wm * 32 + mt * 16 + g + half * 8;
            int dst = (EPI == EPI_SCATTER) ? scatter_dst(row) : row;
#pragma unroll
            for (int nt = 0; nt < 6; nt++) {
                int col = wn * 48 + nt * 8 + tq * 2;
                float v0 = acc[mt][nt][half * 2 + 0] + bias[col];
                float v1 = acc[mt][nt][half * 2 + 1] + bias[col + 1];
                size_t o = (size_t)dst * Nout + col;
                float2 rv = *(const float2*)(res + o);
                float2 w; w.x = v0 + rv.x; w.y = v1 + rv.y;
                *(float2*)(outf + o) = w;
            }
        }
    }
}

// ---------------- proj GEMM + scatter + residual + fused LN2 ----------------
__global__ __launch_bounds__(256, 2)
void gemm_proj_ln(const __nv_bfloat16* __restrict__ Aact,
                  const __nv_bfloat16* __restrict__ Bw,
                  const float* __restrict__ bias, const float* __restrict__ res,
                  float* __restrict__ outx, __nv_bfloat16* __restrict__ outln,
                  const float* __restrict__ gamma, const float* __restrict__ beta,
                  int K) {
    extern __shared__ __align__(16) char smem[];
    const int Nout = 192;
    int tid = threadIdx.x;
    int wid = tid >> 5, lid = tid & 31;
    int wm = wid & 1, wn = wid >> 1;
    int mBase = blockIdx.y * BM2;
    uint32_t sb = smem_u32(smem);

    float acc[2][6][4];
#pragma unroll
    for (int a = 0; a < 2; a++)
#pragma unroll
        for (int b = 0; b < 6; b++)
#pragma unroll
            for (int c = 0; c < 4; c++) acc[a][b][c] = 0.0f;

    int nch = K / BK;

    auto issue = [&](int c) {
        uint32_t sbase = sb + (c % NSTAGE) * STAGE2;
        int k0 = c * BK;
#pragma unroll
        for (int u = 0; u < 4; u++) {
            int ch = tid + u * 256;
            if (ch < 256) {
                int r = ch >> 2, cc = ch & 3;
                cp16(sbase + r * RPB + cc * 16,
                     Aact + (size_t)(mBase + r) * K + k0 + cc * 8);
            } else {
                int q = ch - 256, r = q >> 2, cc = q & 3;
                cp16(sbase + OFF_B2 + r * RPB + cc * 16,
                     Bw + (size_t)r * K + k0 + cc * 8);
            }
        }
        cp_commit();
    };

    int aRow = wm * 32 + (lid & 7) + ((lid >> 3) & 1) * 8;
    int aKof = (lid >> 4) * 16;
    int bRow = wn * 48 + (lid & 7) + ((lid >> 4) & 1) * 8;
    int bKof = ((lid >> 3) & 1) * 16;

    issue(0);
    if (nch > 1) issue(1);
    if (nch > 2) issue(2);
    for (int c = 0; c < nch; c++) {
        int rem = nch - 1 - c;
        if (c + 3 < nch) issue(c + 3);
        if (rem >= 3)      cp_wait<3>();
        else if (rem == 2) cp_wait<2>();
        else if (rem == 1) cp_wait<1>();
        else               cp_wait<0>();
        __syncthreads();

        uint32_t buf = sb + (c % NSTAGE) * STAGE2;
#pragma unroll
        for (int kb = 0; kb < 64; kb += 32) {
            uint32_t ahf[2][4], bhf[3][4];
#pragma unroll
            for (int mt = 0; mt < 2; mt++)
                ldsm_x4(ahf[mt], buf + (aRow + mt * 16) * RPB + kb + aKof);
#pragma unroll
            for (int nb = 0; nb < 3; nb++)
                ldsm_x4(bhf[nb], buf + OFF_B2 + (bRow + nb * 16) * RPB + kb + bKof);
#pragma unroll
            for (int mt = 0; mt < 2; mt++)
#pragma unroll
                for (int nt = 0; nt < 6; nt++)
                    mma16816(acc[mt][nt], ahf[mt], bhf[nt >> 1] + (nt & 1) * 2);
        }
        __syncthreads();
    }

    // ---- epilogue: x = acc + bias + residual; write x; fused LN -> outln ----
    int g = lid >> 2, tq = lid & 3;
    int dsts[2][2];
    float psum[2][2], psq[2][2];
#pragma unroll
    for (int mt = 0; mt < 2; mt++) {
#pragma unroll
        for (int half = 0; half < 2; half++) {
            int row = mBase + wm * 32 + mt * 16 + g + half * 8;
            int dst = scatter_dst(row);
            dsts[mt][half] = dst;
            float s = 0.0f, sq = 0.0f;
#pragma unroll
            for (int nt = 0; nt < 6; nt++) {
                int col = wn * 48 + nt * 8 + tq * 2;
                size_t o = (size_t)dst * Nout + col;
                float2 rv = *(const float2*)(res + o);
                float v0 = acc[mt][nt][half * 2 + 0] + bias[col] + rv.x;
                float v1 = acc[mt][nt][half * 2 + 1] + bias[col + 1] + rv.y;
                acc[mt][nt][half * 2 + 0] = v0;
                acc[mt][nt][half * 2 + 1] = v1;
                float2 w; w.x = v0; w.y = v1;
                *(float2*)(outx + o) = w;
                s += v0 + v1;
                sq += v0 * v0 + v1 * v1;
            }
            s  += __shfl_xor_sync(0xffffffffu, s, 1);
            s  += __shfl_xor_sync(0xffffffffu, s, 2);
            sq += __shfl_xor_sync(0xffffffffu, sq, 1);
            sq += __shfl_xor_sync(0xffffffffu, sq, 2);
            psum[mt][half] = s;
            psq[mt][half] = sq;
        }
    }
    float2* part = (float2*)smem;   // [64 rows][4 wn]
    __syncthreads();
#pragma unroll
    for (int mt = 0; mt < 2; mt++)
#pragma unroll
        for (int half = 0; half < 2; half++) {
            int rloc = wm * 32 + mt * 16 + g + half * 8;
            if (tq == 0) part[rloc * 4 + wn] = make_float2(psum[mt][half], psq[mt][half]);
        }
    __syncthreads();
#pragma unroll
    for (int mt = 0; mt < 2; mt++) {
#pragma unroll
        for (int half = 0; half < 2; half++) {
            int rloc = wm * 32 + mt * 16 + g + half * 8;
            float2 p0 = part[rloc * 4 + 0], p1 = part[rloc * 4 + 1];
            float2 p2 = part[rloc * 4 + 2], p3 = part[rloc * 4 + 3];
            float s = p0.x + p1.x + p2.x + p3.x;
            float sq = p0.y + p1.y + p2.y + p3.y;
            float mean = s * (1.0f / 192.0f);
            float var = sq * (1.0f / 192.0f) - mean * mean;
            float rstd = rsqrtf(var + 1e-5f);
            int dst = dsts[mt][half];
#pragma unroll
            for (int nt = 0; nt < 6; nt++) {
                int col = wn * 48 + nt * 8 + tq * 2;
                float v0 = (acc[mt][nt][half * 2 + 0] - mean) * rstd * gamma[col] + beta[col];
                float v1 = (acc[mt][nt][half * 2 + 1] - mean) * rstd * gamma[col + 1] + beta[col + 1];
                __nv_bfloat162 hp;
                hp.x = __float2bfloat16(v0); hp.y = __float2bfloat16(v1);
                *(__nv_bfloat162*)(outln + (size_t)dst * Nout + col) = hp;
            }
        }
    }
}

// ---------------- Windowed attention: mma.sync + register softmax ----------------
__global__ __launch_bounds__(256)
void attn_kernel(const __nv_bfloat16* __restrict__ qkv,
                 const float* __restrict__ rpb,
                 __nv_bfloat16* __restrict__ oh) {
    extern __shared__ __align__(16) char smem[];
    __shared__ int Ls[49];
    __shared__ int Rs[2][49];

    int tid = threadIdx.x;
    int wid = tid >> 5, lid = tid & 31;
    int ph = wid >> 2;
    int t  = wid & 3;
    int wtid = tid & 127;
    int pair = blockIdx.x * 2 + ph;
    int w = pair / NHEADS;
    int h = pair - w * NHEADS;

    char* sm = smem + ph * PAIR_STRIDE;
    uint32_t sb = smem_u32(smem) + ph * PAIR_STRIDE;
    const float scale = 0.17677669529663687f;

    int r = w & 255;
    int wi = r >> 4, wj = r & 15;

    if (tid < 49) Ls[tid] = 13 * (tid / 7) + tid % 7;
    if (wtid < 49) {
        int i = wtid / 7, j = wtid % 7;
        int hp = wi * 7 + i, wp = wj * 7 + j;
        Rs[ph][wtid] = (hp < 105 ? 0 : (hp < 109 ? 1 : 2)) * 3 + (wp < 105 ? 0 : (wp < 109 ? 1 : 2));
    }

    // vectorized loads: Q,K,V row-major [n][d] pitch 80, uint4 stores
    for (int idx = wtid; idx < 196; idx += 128) {
        int n = idx >> 2, c = idx & 3;
        size_t base = ((size_t)(w * 49 + n)) * (3 * C_DIM) + h * HDIM + c * 8;
        *(uint4*)(sm + AQ + n * 80 + c * 16) = *(const uint4*)(qkv + base);
        *(uint4*)(sm + AK + n * 80 + c * 16) = *(const uint4*)(qkv + base + C_DIM);
        *(uint4*)(sm + AV + n * 80 + c * 16) = *(const uint4*)(qkv + base + 2 * C_DIM);
    }
    // zero V rows m=49..63
    for (int idx = wtid; idx < 60; idx += 128) {
        int n = 49 + idx / 4, c = idx & 3;
        *(uint4*)(sm + AV + n * 80 + c * 16) = make_uint4(0, 0, 0, 0);
    }
    __syncthreads();

    int aRow = t * 16 + (lid & 7) + ((lid >> 3) & 1) * 8;
    int aKof = (lid >> 4) * 16;
    int bRowB = (lid & 7) + ((lid >> 4) & 1) * 8;
    int bKof = ((lid >> 3) & 1) * 16;
    int vRow = (lid & 7) + ((lid >> 3) & 1) * 8;
    int vCol = ((lid >> 4) & 1) * 16;
    int g = lid >> 2, tq = lid & 3;

    // ---- S = Q K^T (64x64x32) into registers ----
    float acc[8][4];
#pragma unroll
    for (int a = 0; a < 8; a++)
#pragma unroll
        for (int c = 0; c < 4; c++) acc[a][c] = 0.0f;
#pragma unroll
    for (int kb = 0; kb < 64; kb += 32) {
        uint32_t af[4];
        ldsm_x4(af, sb + AQ + aRow * 80 + kb + aKof);
#pragma unroll
        for (int nb = 0; nb < 4; nb++) {
            uint32_t bf[4];
            ldsm_x4(bf, sb + AK + (bRowB + nb * 16) * 80 + kb + bKof);
            mma16816(acc[2 * nb],     af, bf);
            mma16816(acc[2 * nb + 1], af, bf + 2);
        }
    }
    __syncthreads();   // Q/K reads complete before P overwrites them

    // ---- register softmax per half-row (row in 4 lanes: tq quads) + write bf16 P ----
    char* pb = sm + APB;
#pragma unroll
    for (int half = 0; half < 2; half++) {
        int row = t * 16 + g + half * 8;
        bool valid = row < 49;
        float vs[16];
        float mx = -1e30f;
        if (valid) {
            int L0 = Ls[row] + 84, R0 = Rs[ph][row];
#pragma unroll
            for (int nt = 0; nt < 8; nt++) {
#pragma unroll
                for (int e = 0; e < 2; e++) {
                    int cc = nt * 8 + tq * 2 + e;
                    float v = -1e30f;
                    if (cc < 49)
                        v = acc[nt][half * 2 + e] * scale
                          + rpb[(L0 - Ls[cc]) * NHEADS + h]
                          + (R0 == Rs[ph][cc] ? 0.0f : -100.0f);
                    vs[nt * 2 + e] = v;
                    mx = fmaxf(mx, v);
                }
            }
        }
        mx = fmaxf(mx, __shfl_xor_sync(0xffffffffu, mx, 1));
        mx = fmaxf(mx, __shfl_xor_sync(0xffffffffu, mx, 2));
        float sum = 0.0f;
        if (valid) {
#pragma unroll
            for (int i = 0; i < 16; i++) {
                float e = __expf(vs[i] - mx);
                vs[i] = e;
                sum += e;
            }
        }
        sum += __shfl_xor_sync(0xffffffffu, sum, 1);
        sum += __shfl_xor_sync(0xffffffffu, sum, 2);
        float inv = valid ? (1.0f / sum) : 0.0f;
#pragma unroll
        for (int nt = 0; nt < 8; nt++) {
            __nv_bfloat162 hp;
            hp.x = __float2bfloat16(valid ? vs[nt * 2 + 0] * inv : 0.0f);
            hp.y = __float2bfloat16(valid ? vs[nt * 2 + 1] * inv : 0.0f);
            *(__nv_bfloat162*)(pb + row * 144 + (nt * 8 + tq * 2) * 2) = hp;
        }
    }
    __syncthreads();

    // ---- O = P V (64x32x64), V via trans-ldsm from row-major [m][d] ----
    {
        float oacc[4][4];
#pragma unroll
        for (int a = 0; a < 4; a++)
#pragma unroll
            for (int c = 0; c < 4; c++) oacc[a][c] = 0.0f;
#pragma unroll
        for (int ks = 0; ks < 4; ks++) {
            int kb = ks * 32;
            uint32_t af[4];
            ldsm_x4(af, sb + APB + aRow * 144 + kb + aKof);
            uint32_t bf0[4], bf1[4];
            uint32_t vbase = sb + AV + (ks * 16 + vRow) * 80 + vCol;
            ldsm_x4_t(bf0, vbase);
            ldsm_x4_t(bf1, vbase + 32);
            mma16816(oacc[0], af, bf0);
            mma16816(oacc[1], af, bf0 + 2);
            mma16816(oacc[2], af, bf1);
            mma16816(oacc[3], af, bf1 + 2);
        }
#pragma unroll
        for (int half = 0; half < 2; half++) {
            int row = t * 16 + g + half * 8;
            if (row < 49) {
#pragma unroll
                for (int nt = 0; nt < 4; nt++) {
                    int col = nt * 8 + tq * 2;
                    __nv_bfloat162 hp;
                    hp.x = __float2bfloat16(oacc[nt][half * 2 + 0]);
                    hp.y = __float2bfloat16(oacc[nt][half * 2 + 1]);
                    size_t o = ((size_t)(w * 49 + row)) * C_DIM + h * HDIM + col;
                    *(__nv_bfloat162*)(oh + o) = hp;
                }
            }
        }
    }
}

// ---------------- launch ----------------
extern "C" void kernel_launch(void* const* d_in, const int* in_sizes, int n_in,
                              void* d_out, int out_size) {
    const float* query   = (const float*)d_in[0];
    const float* norm1_g = (const float*)d_in[1];
    const float* norm1_b = (const float*)d_in[2];
    const float* qkv_w   = (const float*)d_in[3];
    const float* qkv_b   = (const float*)d_in[4];
    const float* rpb     = (const float*)d_in[5];
    const float* proj_w  = (const float*)d_in[6];
    const float* proj_b  = (const float*)d_in[7];
    const float* norm2_g = (const float*)d_in[8];
    const float* norm2_b = (const float*)d_in[9];
    const float* fc1_w   = (const float*)d_in[10];
    const float* fc1_b   = (const float*)d_in[11];
    const float* fc2_w   = (const float*)d_in[12];
    const float* fc2_b   = (const float*)d_in[13];
    float* out = (float*)d_out;

    __nv_bfloat16 *xw, *qkvp, *att, *ln2, *hbuf;
    __nv_bfloat16 *wq, *wp, *w1, *w2;
    float *x;
    cudaGetSymbolAddress((void**)&xw, g_xw);
    cudaGetSymbolAddress((void**)&qkvp, g_qkv);
    cudaGetSymbolAddress((void**)&att, g_att);
    cudaGetSymbolAddress((void**)&x, g_x);
    cudaGetSymbolAddress((void**)&ln2, g_ln2);
    cudaGetSymbolAddress((void**)&hbuf, g_h);
    cudaGetSymbolAddress((void**)&wq, g_wqkv);
    cudaGetSymbolAddress((void**)&wp, g_wprj);
    cudaGetSymbolAddress((void**)&w1, g_wfc1);
    cudaGetSymbolAddress((void**)&w2, g_wfc2);

    const int SMEM  = NSTAGE * STAGE_BYTES;  // 61440
    const int SMEM2 = NSTAGE * STAGE2;       // 81920
    cudaFuncSetAttribute(gemm_mma<EPI_BF16>, cudaFuncAttributeMaxDynamicSharedMemorySize, SMEM);
    cudaFuncSetAttribute(gemm_mma<EPI_GELU>, cudaFuncAttributeMaxDynamicSharedMemorySize, SMEM);
    cudaFuncSetAttribute(gemm_proj_ln,       cudaFuncAttributeMaxDynamicSharedMemorySize, SMEM2);
    cudaFuncSetAttribute(gemm_mma_n192<EPI_RES>, cudaFuncAttributeMaxDynamicSharedMemorySize, SMEM2);
    cudaFuncSetAttribute(attn_kernel, cudaFuncAttributeMaxDynamicSharedMemorySize, ATTN_SMEM);

    wprep_all<<<(442368 + 255) / 256, 256>>>(qkv_w, proj_w, fc1_w, fc2_w, wq, wp, w1, w2);

    // 1) LN1 + shift + window partition
    ln_kernel<true><<<M_TOK, 192>>>(query, norm1_g, norm1_b, xw);

    // 2) qkv  [100352,192] x [192,576] -> bf16
    gemm_mma<EPI_BF16><<<dim3(576 / BN, M_TOK / BM), 256, SMEM>>>(
        xw, wq, qkv_b, nullptr, nullptr, qkvp, 192, 576);

    // 3) windowed attention (register softmax)
    attn_kernel<<<2048 * NHEADS / 2, 256, ATTN_SMEM>>>(qkvp, rpb, att);

    // 4) proj + window reverse + unshift + residual(query) + fused LN2
    gemm_proj_ln<<<dim3(1, M_TOK / BM2), 256, SMEM2>>>(
        att, wp, proj_b, query, x, ln2, norm2_g, norm2_b, 192);

    // 5) fc1 + GELU
    gemm_mma<EPI_GELU><<<dim3(768 / BN, M_TOK / BM), 256, SMEM>>>(
        ln2, w1, fc1_b, nullptr, nullptr, hbuf, 192, 768);

    // 6) fc2 + residual(x) -> out
    gemm_mma_n192<EPI_RES><<<dim3(1, M_TOK / BM2), 256, SMEM2>>>(
        hbuf, w2, fc2_b, x, out, 768);
}